// round 7
// baseline (speedup 1.0000x reference)
#include <cuda_runtime.h>
#include <cuda_bf16.h>

#define NUM_NODES 10000
#define N_EDGES   640000
#define D         128
#define BUCKET    128
#define OVF_MAX   4096

// ---------------- device scratch ----------------
__device__ float d_S[NUM_NODES * D];
__device__ float d_A[NUM_NODES * D];
__device__ int   d_cur[NUM_NODES];
__device__ float d_degf[NUM_NODES];
__device__ int2  d_perm2[NUM_NODES * BUCKET];
__device__ int3  d_ovf[OVF_MAX];
__device__ int   d_ovf_cnt;
__device__ float d_Mf[512 * D];
__device__ float d_cvec[D];
__device__ int   d_is64;

// ---------------- helpers ----------------
__device__ __forceinline__ int load_idx(const void* ei, int which, int e, int is64) {
    if (is64) {
        const long long* p = (const long long*)ei;
        return (int)__ldg(p + (size_t)which * N_EDGES + e);
    } else {
        const int* p = (const int*)ei;
        return __ldg(p + (size_t)which * N_EDGES + e);
    }
}
__device__ __forceinline__ float4 ldg4(const float* p)  { return __ldg((const float4*)p); }
__device__ __forceinline__ float4 ldcs4(const float* p) { return __ldcs((const float4*)p); }

// ---------------- K0: setup = weight fusion + dtype probe + counter zeroing ----------------
__global__ void k_setup(const float* __restrict__ W1,
                        const float* __restrict__ b1,
                        const float* __restrict__ W2,
                        const int*   __restrict__ ei_words) {
    int r = blockIdx.x, o = threadIdx.x;   // 128 threads
    if (r >= 512) {
        if (r == 512) {
            int w = ei_words[2 * o + 1];   // high words if int64
            int any = __syncthreads_or(w != 0);
            if (o == 0) { d_is64 = (any == 0) ? 1 : 0; d_ovf_cnt = 0; }
        } else {
            int i = (r - 513) * 128 + o;
            if (i < NUM_NODES) d_cur[i] = 0;
        }
        return;
    }
    __shared__ float row[D];
    if (r >= 256 && r < 384) {
        d_Mf[r * D + o] = W2[(128 + (r - 256)) * D + o];
        return;
    }
    int w1row = (r < 128) ? r : (r < 256) ? (256 + (r - 128)) : (128 + (r - 384));
    row[o] = W1[w1row * D + o];
    __syncthreads();
    float acc = 0.f;
#pragma unroll 8
    for (int h = 0; h < D; h++) acc += row[h] * __ldg(W2 + h * D + o);
    d_Mf[r * D + o] = acc;
    if (r == 0) {
        __syncthreads();
        row[o] = b1[o];
        __syncthreads();
        float c = 0.f;
#pragma unroll 8
        for (int h = 0; h < D; h++) c += row[h] * __ldg(W2 + h * D + o);
        d_cvec[o] = c;
    }
}

// ---------------- K1: single-pass bucket scatter ----------------
__global__ void k_scatter(const void* ei) {
    int is64 = d_is64;
    int e = blockIdx.x * blockDim.x + threadIdx.x;
    if (e >= N_EDGES) return;
    int dst = load_idx(ei, 1, e, is64);
    int src = load_idx(ei, 0, e, is64);
    int pos = atomicAdd(&d_cur[dst], 1);
    if (pos < BUCKET) {
        d_perm2[(dst << 7) + pos] = make_int2(e, src);
    } else {
        int o = atomicAdd(&d_ovf_cnt, 1);
        if (o < OVF_MAX) d_ovf[o] = make_int3(dst, e, src);
    }
}

// ---------------- K2: atomic-free segment sums (known-good) ----------------
__global__ void k_agg(const float* __restrict__ x, const float* __restrict__ ea) {
    int n = blockIdx.x * 4 + (threadIdx.x >> 5);
    if (n >= NUM_NODES) return;
    int lane = threadIdx.x & 31;
    int deg = d_cur[n];
    if (lane == 0) d_degf[n] = (float)deg;
    int cnt = min(deg, BUCKET);
    const int2* bucket = d_perm2 + ((size_t)n << 7);

    float4 aS = make_float4(0.f, 0.f, 0.f, 0.f);
    float4 aA = make_float4(0.f, 0.f, 0.f, 0.f);

    int j = 0;
    for (; j + 4 <= cnt; j += 4) {
        int2 p0 = __ldg(bucket + j + 0);
        int2 p1 = __ldg(bucket + j + 1);
        int2 p2 = __ldg(bucket + j + 2);
        int2 p3 = __ldg(bucket + j + 3);
        float4 x0 = ldg4(x + (size_t)p0.y * D + lane * 4);
        float4 x1 = ldg4(x + (size_t)p1.y * D + lane * 4);
        float4 x2 = ldg4(x + (size_t)p2.y * D + lane * 4);
        float4 x3 = ldg4(x + (size_t)p3.y * D + lane * 4);
        float4 a0 = ldcs4(ea + (size_t)p0.x * D + lane * 4);
        float4 a1 = ldcs4(ea + (size_t)p1.x * D + lane * 4);
        float4 a2 = ldcs4(ea + (size_t)p2.x * D + lane * 4);
        float4 a3 = ldcs4(ea + (size_t)p3.x * D + lane * 4);
        aS.x += (x0.x + x1.x) + (x2.x + x3.x);
        aS.y += (x0.y + x1.y) + (x2.y + x3.y);
        aS.z += (x0.z + x1.z) + (x2.z + x3.z);
        aS.w += (x0.w + x1.w) + (x2.w + x3.w);
        aA.x += (a0.x + a1.x) + (a2.x + a3.x);
        aA.y += (a0.y + a1.y) + (a2.y + a3.y);
        aA.z += (a0.z + a1.z) + (a2.z + a3.z);
        aA.w += (a0.w + a1.w) + (a2.w + a3.w);
    }
    for (; j < cnt; j++) {
        int2 p = __ldg(bucket + j);
        float4 xv = ldg4(x + (size_t)p.y * D + lane * 4);
        float4 av = ldcs4(ea + (size_t)p.x * D + lane * 4);
        aS.x += xv.x; aS.y += xv.y; aS.z += xv.z; aS.w += xv.w;
        aA.x += av.x; aA.y += av.y; aA.z += av.z; aA.w += av.w;
    }

    if (deg > BUCKET) {
        int cnt_o = d_ovf_cnt;
        if (cnt_o > OVF_MAX) cnt_o = OVF_MAX;
        for (int i = 0; i < cnt_o; i++) {
            int3 v = d_ovf[i];
            if (v.x == n) {
                float4 xv = ldg4(x + (size_t)v.z * D + lane * 4);
                float4 av = ldg4(ea + (size_t)v.y * D + lane * 4);
                aS.x += xv.x; aS.y += xv.y; aS.z += xv.z; aS.w += xv.w;
                aA.x += av.x; aA.y += av.y; aA.z += av.z; aA.w += av.w;
            }
        }
    }

    *(float4*)(d_S + (size_t)n * D + lane * 4) = aS;
    *(float4*)(d_A + (size_t)n * D + lane * 4) = aA;
}

// ---------------- K3: fused node GEMM — warp-per-output-group, K split across 2 warpgroups ----
// Block: 32 nodes x 128 outs, 512 threads = 2 warpgroups of 8 warps.
// Warpgroup wg handles k in [256*wg, 256*wg+256) with its own Us/Ms buffers
// and named barrier (1+wg). Partials combined through smem at the end.
__global__ void __launch_bounds__(512, 2)
k_gemm(const float* __restrict__ x,
       const float* __restrict__ b2,
       float* __restrict__ out) {
    __shared__ float Us[2][32 * 33];
    __shared__ float Ms[2][32 * 128];
    int tid = threadIdx.x;
    int wg = tid >> 8;        // warpgroup 0/1
    int t = tid & 255;        // id within warpgroup
    int w = t >> 5;           // output group (8 per warpgroup, same 8 groups each)
    int lane = t & 31;        // node within tile
    int n0 = blockIdx.x * 32;

    float acc[16];
#pragma unroll
    for (int j = 0; j < 16; j++) acc[j] = 0.f;

    int kbeg = wg * 256;
    for (int k0 = kbeg; k0 < kbeg + 256; k0 += 32) {
        int region = k0 >> 7;
        int kloc = k0 & 127;
        const float* base = (region == 0) ? d_S : (region == 1) ? d_A : x;

        // U tile: 32x32 floats, one float4 per thread of this warpgroup
        {
            int r = t >> 3, c = (t & 7) * 4;
            int nn = n0 + r;
            float4 val = make_float4(0.f, 0.f, 0.f, 0.f);
            if (nn < NUM_NODES) {
                val = ldg4(base + (size_t)nn * D + kloc + c);
                if (region == 3) {
                    float dg = d_degf[nn];
                    val.x *= dg; val.y *= dg; val.z *= dg; val.w *= dg;
                }
            }
            Us[wg][r * 33 + c + 0] = val.x;
            Us[wg][r * 33 + c + 1] = val.y;
            Us[wg][r * 33 + c + 2] = val.z;
            Us[wg][r * 33 + c + 3] = val.w;
        }
        // M tile: 32x128 floats, 4 float4 per thread of this warpgroup
#pragma unroll
        for (int v = 0; v < 4; v++) {
            int id = t * 16 + v * 4;
            int r = id >> 7, c = id & 127;
            *(float4*)(&Ms[wg][r * 128 + c]) = ldg4(d_Mf + (size_t)(k0 + r) * 128 + c);
        }
        asm volatile("bar.sync %0, %1;" :: "r"(1 + wg), "r"(256) : "memory");

#pragma unroll
        for (int kk = 0; kk < 32; kk++) {
            float u = Us[wg][lane * 33 + kk];             // conflict-free
            const float4* mrow = (const float4*)(&Ms[wg][kk * 128 + w * 16]);
            float4 m0 = mrow[0];                          // warp-broadcast
            float4 m1 = mrow[1];
            float4 m2 = mrow[2];
            float4 m3 = mrow[3];
            acc[ 0] += u * m0.x; acc[ 1] += u * m0.y; acc[ 2] += u * m0.z; acc[ 3] += u * m0.w;
            acc[ 4] += u * m1.x; acc[ 5] += u * m1.y; acc[ 6] += u * m1.z; acc[ 7] += u * m1.w;
            acc[ 8] += u * m2.x; acc[ 9] += u * m2.y; acc[10] += u * m2.z; acc[11] += u * m2.w;
            acc[12] += u * m3.x; acc[13] += u * m3.y; acc[14] += u * m3.z; acc[15] += u * m3.w;
        }
        asm volatile("bar.sync %0, %1;" :: "r"(1 + wg), "r"(256) : "memory");
    }

    // combine: warpgroup 1 dumps partials into its Ms buffer (dead now), wg0 adds
    float* red = &Ms[1][0];     // 32 nodes x 128 outs
    if (wg == 1) {
#pragma unroll
        for (int j = 0; j < 16; j++) red[lane * 128 + w * 16 + j] = acc[j];
    }
    __syncthreads();
    if (wg == 0) {
        int n = n0 + lane;
        if (n < NUM_NODES) {
            float dg = d_degf[n];
            float o16[16];
#pragma unroll
            for (int j = 0; j < 16; j++) {
                int o = w * 16 + j;
                o16[j] = acc[j] + red[lane * 128 + o] + dg * d_cvec[o] + b2[o];
            }
            float4* outp = (float4*)(out + (size_t)n * D + w * 16);
            outp[0] = make_float4(o16[ 0], o16[ 1], o16[ 2], o16[ 3]);
            outp[1] = make_float4(o16[ 4], o16[ 5], o16[ 6], o16[ 7]);
            outp[2] = make_float4(o16[ 8], o16[ 9], o16[10], o16[11]);
            outp[3] = make_float4(o16[12], o16[13], o16[14], o16[15]);
        }
    }
}

// ---------------- launch ----------------
extern "C" void kernel_launch(void* const* d_in, const int* in_sizes, int n_in,
                              void* d_out, int out_size) {
    const float* x  = (const float*)d_in[0];
    const void*  ei = d_in[1];
    const float* ea = (const float*)d_in[2];
    const float* W1 = (const float*)d_in[3];
    const float* b1 = (const float*)d_in[4];
    const float* W2 = (const float*)d_in[5];
    const float* b2 = (const float*)d_in[6];
    float* out = (float*)d_out;

    k_setup<<<592, 128>>>(W1, b1, W2, (const int*)ei);
    k_scatter<<<(N_EDGES + 255) / 256, 256>>>(ei);
    k_agg<<<(NUM_NODES + 3) / 4, 128>>>(x, ea);
    k_gemm<<<(NUM_NODES + 31) / 32, 512>>>(x, b2, out);
}

// round 8
// speedup vs baseline: 1.5986x; 1.5986x over previous
#include <cuda_runtime.h>
#include <cuda_bf16.h>

#define NUM_NODES 10000
#define N_EDGES   640000
#define D         128
#define BUCKET    128
#define OVF_MAX   4096

// ---------------- device scratch ----------------
__device__ float d_S[NUM_NODES * D];
__device__ float d_A[NUM_NODES * D];
__device__ int   d_cur[NUM_NODES];
__device__ float d_degf[NUM_NODES];
__device__ int2  d_perm2[NUM_NODES * BUCKET];
__device__ int3  d_ovf[OVF_MAX];
__device__ int   d_ovf_cnt;
__device__ float d_Mf[512 * D];
__device__ float d_cvec[D];
__device__ int   d_is64;

// ---------------- helpers ----------------
__device__ __forceinline__ int load_idx(const void* ei, int which, int e, int is64) {
    if (is64) {
        const long long* p = (const long long*)ei;
        return (int)__ldg(p + (size_t)which * N_EDGES + e);
    } else {
        const int* p = (const int*)ei;
        return __ldg(p + (size_t)which * N_EDGES + e);
    }
}
__device__ __forceinline__ float4 ldg4(const float* p)  { return __ldg((const float4*)p); }
__device__ __forceinline__ float4 ldcs4(const float* p) { return __ldcs((const float4*)p); }

// ---------------- K0: setup = weight fusion + dtype probe + counter zeroing ----------------
__global__ void k_setup(const float* __restrict__ W1,
                        const float* __restrict__ b1,
                        const float* __restrict__ W2,
                        const int*   __restrict__ ei_words) {
    int r = blockIdx.x, o = threadIdx.x;   // 128 threads
    if (r >= 512) {
        if (r == 512) {
            int w = ei_words[2 * o + 1];   // high words if int64
            int any = __syncthreads_or(w != 0);
            if (o == 0) { d_is64 = (any == 0) ? 1 : 0; d_ovf_cnt = 0; }
        } else {
            int i = (r - 513) * 128 + o;
            if (i < NUM_NODES) d_cur[i] = 0;
        }
        return;
    }
    __shared__ float row[D];
    if (r >= 256 && r < 384) {
        d_Mf[r * D + o] = W2[(128 + (r - 256)) * D + o];
        return;
    }
    int w1row = (r < 128) ? r : (r < 256) ? (256 + (r - 128)) : (128 + (r - 384));
    row[o] = W1[w1row * D + o];
    __syncthreads();
    float acc = 0.f;
#pragma unroll 8
    for (int h = 0; h < D; h++) acc += row[h] * __ldg(W2 + h * D + o);
    d_Mf[r * D + o] = acc;
    if (r == 0) {
        __syncthreads();
        row[o] = b1[o];
        __syncthreads();
        float c = 0.f;
#pragma unroll 8
        for (int h = 0; h < D; h++) c += row[h] * __ldg(W2 + h * D + o);
        d_cvec[o] = c;
    }
}

// ---------------- K1: single-pass bucket scatter ----------------
__global__ void k_scatter(const void* ei) {
    int is64 = d_is64;
    int e = blockIdx.x * blockDim.x + threadIdx.x;
    if (e >= N_EDGES) return;
    int dst = load_idx(ei, 1, e, is64);
    int src = load_idx(ei, 0, e, is64);
    int pos = atomicAdd(&d_cur[dst], 1);
    if (pos < BUCKET) {
        d_perm2[(dst << 7) + pos] = make_int2(e, src);
    } else {
        int o = atomicAdd(&d_ovf_cnt, 1);
        if (o < OVF_MAX) d_ovf[o] = make_int3(dst, e, src);
    }
}

// ---------------- K2: atomic-free segment sums (known-good) ----------------
__global__ void k_agg(const float* __restrict__ x, const float* __restrict__ ea) {
    int n = blockIdx.x * 4 + (threadIdx.x >> 5);
    if (n >= NUM_NODES) return;
    int lane = threadIdx.x & 31;
    int deg = d_cur[n];
    if (lane == 0) d_degf[n] = (float)deg;
    int cnt = min(deg, BUCKET);
    const int2* bucket = d_perm2 + ((size_t)n << 7);

    float4 aS = make_float4(0.f, 0.f, 0.f, 0.f);
    float4 aA = make_float4(0.f, 0.f, 0.f, 0.f);

    int j = 0;
    for (; j + 4 <= cnt; j += 4) {
        int2 p0 = __ldg(bucket + j + 0);
        int2 p1 = __ldg(bucket + j + 1);
        int2 p2 = __ldg(bucket + j + 2);
        int2 p3 = __ldg(bucket + j + 3);
        float4 x0 = ldg4(x + (size_t)p0.y * D + lane * 4);
        float4 x1 = ldg4(x + (size_t)p1.y * D + lane * 4);
        float4 x2 = ldg4(x + (size_t)p2.y * D + lane * 4);
        float4 x3 = ldg4(x + (size_t)p3.y * D + lane * 4);
        float4 a0 = ldcs4(ea + (size_t)p0.x * D + lane * 4);
        float4 a1 = ldcs4(ea + (size_t)p1.x * D + lane * 4);
        float4 a2 = ldcs4(ea + (size_t)p2.x * D + lane * 4);
        float4 a3 = ldcs4(ea + (size_t)p3.x * D + lane * 4);
        aS.x += (x0.x + x1.x) + (x2.x + x3.x);
        aS.y += (x0.y + x1.y) + (x2.y + x3.y);
        aS.z += (x0.z + x1.z) + (x2.z + x3.z);
        aS.w += (x0.w + x1.w) + (x2.w + x3.w);
        aA.x += (a0.x + a1.x) + (a2.x + a3.x);
        aA.y += (a0.y + a1.y) + (a2.y + a3.y);
        aA.z += (a0.z + a1.z) + (a2.z + a3.z);
        aA.w += (a0.w + a1.w) + (a2.w + a3.w);
    }
    for (; j < cnt; j++) {
        int2 p = __ldg(bucket + j);
        float4 xv = ldg4(x + (size_t)p.y * D + lane * 4);
        float4 av = ldcs4(ea + (size_t)p.x * D + lane * 4);
        aS.x += xv.x; aS.y += xv.y; aS.z += xv.z; aS.w += xv.w;
        aA.x += av.x; aA.y += av.y; aA.z += av.z; aA.w += av.w;
    }

    if (deg > BUCKET) {
        int cnt_o = d_ovf_cnt;
        if (cnt_o > OVF_MAX) cnt_o = OVF_MAX;
        for (int i = 0; i < cnt_o; i++) {
            int3 v = d_ovf[i];
            if (v.x == n) {
                float4 xv = ldg4(x + (size_t)v.z * D + lane * 4);
                float4 av = ldg4(ea + (size_t)v.y * D + lane * 4);
                aS.x += xv.x; aS.y += xv.y; aS.z += xv.z; aS.w += xv.w;
                aA.x += av.x; aA.y += av.y; aA.z += av.z; aA.w += av.w;
            }
        }
    }

    *(float4*)(d_S + (size_t)n * D + lane * 4) = aS;
    *(float4*)(d_A + (size_t)n * D + lane * 4) = aA;
}

// ---------------- K3: fused node GEMM — warp-per-output-group, output-split grid ----------------
// Block: 32 nodes x 64 outputs, 256 threads (8 warps). blockIdx.y selects output half.
// Warp w owns outputs [obase + 8w, obase + 8w + 8); lane owns one node.
// grid = (313, 2) = 626 blocks -> ~4 blocks/SM -> ~32 warps/SM.
__global__ void __launch_bounds__(256)
k_gemm(const float* __restrict__ x,
       const float* __restrict__ b2,
       float* __restrict__ out) {
    __shared__ float Us[32 * 33];
    __shared__ float Ms[32 * 64];
    int t = threadIdx.x;
    int w = t >> 5;            // output group within block (0..7)
    int lane = t & 31;         // node within tile
    int n0 = blockIdx.x * 32;
    int obase = blockIdx.y * 64;
    int n = n0 + lane;

    float acc[8];
#pragma unroll
    for (int j = 0; j < 8; j++) acc[j] = 0.f;

    for (int k0 = 0; k0 < 512; k0 += 32) {
        int region = k0 >> 7;
        int kloc = k0 & 127;
        const float* base = (region == 0) ? d_S : (region == 1) ? d_A : x;

        // U tile: 32x32 floats, one float4 per thread
        {
            int r = t >> 3, c = (t & 7) * 4;
            int nn = n0 + r;
            float4 val = make_float4(0.f, 0.f, 0.f, 0.f);
            if (nn < NUM_NODES) {
                val = ldg4(base + (size_t)nn * D + kloc + c);
                if (region == 3) {
                    float dg = d_degf[nn];
                    val.x *= dg; val.y *= dg; val.z *= dg; val.w *= dg;
                }
            }
            Us[r * 33 + c + 0] = val.x;
            Us[r * 33 + c + 1] = val.y;
            Us[r * 33 + c + 2] = val.z;
            Us[r * 33 + c + 3] = val.w;
        }
        // M tile: 32 k-rows x 64 outs, 2 float4 per thread
#pragma unroll
        for (int v = 0; v < 2; v++) {
            int id = t * 8 + v * 4;
            int r = id >> 6, c = id & 63;
            *(float4*)(Ms + r * 64 + c) = ldg4(d_Mf + (size_t)(k0 + r) * 128 + obase + c);
        }
        __syncthreads();

#pragma unroll
        for (int kk = 0; kk < 32; kk++) {
            float u = Us[lane * 33 + kk];                 // conflict-free
            const float4* mrow = (const float4*)(Ms + kk * 64 + w * 8);
            float4 m0 = mrow[0];                          // warp-broadcast
            float4 m1 = mrow[1];
            acc[0] += u * m0.x; acc[1] += u * m0.y; acc[2] += u * m0.z; acc[3] += u * m0.w;
            acc[4] += u * m1.x; acc[5] += u * m1.y; acc[6] += u * m1.z; acc[7] += u * m1.w;
        }
        __syncthreads();
    }

    if (n < NUM_NODES) {
        float dg = d_degf[n];
        float o8[8];
#pragma unroll
        for (int j = 0; j < 8; j++) {
            int o = obase + w * 8 + j;
            o8[j] = acc[j] + dg * d_cvec[o] + b2[o];
        }
        float4* outp = (float4*)(out + (size_t)n * D + obase + w * 8);
        outp[0] = make_float4(o8[0], o8[1], o8[2], o8[3]);
        outp[1] = make_float4(o8[4], o8[5], o8[6], o8[7]);
    }
}

// ---------------- launch ----------------
extern "C" void kernel_launch(void* const* d_in, const int* in_sizes, int n_in,
                              void* d_out, int out_size) {
    const float* x  = (const float*)d_in[0];
    const void*  ei = d_in[1];
    const float* ea = (const float*)d_in[2];
    const float* W1 = (const float*)d_in[3];
    const float* b1 = (const float*)d_in[4];
    const float* W2 = (const float*)d_in[5];
    const float* b2 = (const float*)d_in[6];
    float* out = (float*)d_out;

    k_setup<<<592, 128>>>(W1, b1, W2, (const int*)ei);
    k_scatter<<<(N_EDGES + 255) / 256, 256>>>(ei);
    k_agg<<<(NUM_NODES + 3) / 4, 128>>>(x, ea);
    dim3 gg((NUM_NODES + 31) / 32, 2);
    k_gemm<<<gg, 256>>>(x, b2, out);
}

// round 10
// speedup vs baseline: 2.0740x; 1.2973x over previous
#include <cuda_runtime.h>
#include <cuda_bf16.h>
#include <cstdint>

#define NUM_NODES 10000
#define N_EDGES   640000
#define D         128
#define BUCKET    128
#define OVF_MAX   4096

// ---------------- device scratch ----------------
__device__ float d_S[NUM_NODES * D];
__device__ float d_A[NUM_NODES * D];
__device__ int   d_cur[NUM_NODES];
__device__ float d_degf[NUM_NODES];
__device__ int2  d_perm2[NUM_NODES * BUCKET];
__device__ int3  d_ovf[OVF_MAX];
__device__ int   d_ovf_cnt;
__device__ __nv_bfloat16 d_MThi[128 * 512];   // fused weights, transposed [out][k], bf16 hi
__device__ __nv_bfloat16 d_MTlo[128 * 512];   // bf16 lo residual
__device__ float d_cvec[D];                   // b1 @ W2a
__device__ int   d_is64;

// ---------------- helpers ----------------
__device__ __forceinline__ int load_idx(const void* ei, int which, int e, int is64) {
    if (is64) {
        const long long* p = (const long long*)ei;
        return (int)__ldg(p + (size_t)which * N_EDGES + e);
    } else {
        const int* p = (const int*)ei;
        return __ldg(p + (size_t)which * N_EDGES + e);
    }
}
__device__ __forceinline__ float4 ldg4(const float* p)  { return __ldg((const float4*)p); }
__device__ __forceinline__ float4 ldcs4(const float* p) { return __ldcs((const float4*)p); }

__device__ __forceinline__ uint32_t smem_u32(const void* p) {
    uint32_t a;
    asm("{ .reg .u64 t; cvta.to.shared.u64 t, %1; cvt.u32.u64 %0, t; }" : "=r"(a) : "l"(p));
    return a;
}

// bf16 hi/lo split of a float pair -> packed b16x2 words
__device__ __forceinline__ void split2(float a, float b, uint32_t& hi, uint32_t& lo) {
    __nv_bfloat162 h = __floats2bfloat162_rn(a, b);
    float2 hf = __bfloat1622float2(h);
    __nv_bfloat162 l = __floats2bfloat162_rn(a - hf.x, b - hf.y);
    hi = *reinterpret_cast<uint32_t*>(&h);
    lo = *reinterpret_cast<uint32_t*>(&l);
}

__device__ __forceinline__ void ldm_x4(uint32_t& r0, uint32_t& r1, uint32_t& r2, uint32_t& r3,
                                       uint32_t addr) {
    asm volatile("ldmatrix.sync.aligned.m8n8.x4.shared.b16 {%0,%1,%2,%3}, [%4];"
                 : "=r"(r0), "=r"(r1), "=r"(r2), "=r"(r3) : "r"(addr));
}
__device__ __forceinline__ void mma16816(float* c,
                                         uint32_t a0, uint32_t a1, uint32_t a2, uint32_t a3,
                                         uint32_t b0, uint32_t b1) {
    asm volatile(
        "mma.sync.aligned.m16n8k16.row.col.f32.bf16.bf16.f32 "
        "{%0,%1,%2,%3}, {%4,%5,%6,%7}, {%8,%9}, {%0,%1,%2,%3};"
        : "+f"(c[0]), "+f"(c[1]), "+f"(c[2]), "+f"(c[3])
        : "r"(a0), "r"(a1), "r"(a2), "r"(a3), "r"(b0), "r"(b1));
}

// ---------------- K0: setup = weight fusion (fp32->bf16 hi/lo, transposed) + probe + zero ----
__global__ void k_setup(const float* __restrict__ W1,
                        const float* __restrict__ b1,
                        const float* __restrict__ W2,
                        const int*   __restrict__ ei_words) {
    int r = blockIdx.x, o = threadIdx.x;   // 128 threads
    if (r >= 512) {
        if (r == 512) {
            int w = ei_words[2 * o + 1];   // high words if int64
            int any = __syncthreads_or(w != 0);
            if (o == 0) { d_is64 = (any == 0) ? 1 : 0; d_ovf_cnt = 0; }
        } else {
            int i = (r - 513) * 128 + o;
            if (i < NUM_NODES) d_cur[i] = 0;
        }
        return;
    }
    // Fused matrix row r (k-index), column o (output):
    //   [0,128):   W1a@W2a (S)   [128,256): W1c@W2a (A)
    //   [256,384): W2b     (x)   [384,512): W1b@W2a (deg*x)
    __shared__ float row[D];
    float v;
    if (r >= 256 && r < 384) {
        v = W2[(128 + (r - 256)) * D + o];
    } else {
        int w1row = (r < 128) ? r : (r < 256) ? (256 + (r - 128)) : (128 + (r - 384));
        row[o] = W1[w1row * D + o];
        __syncthreads();
        float acc = 0.f;
#pragma unroll 8
        for (int h = 0; h < D; h++) acc += row[h] * __ldg(W2 + h * D + o);
        v = acc;
        if (r == 0) {
            __syncthreads();
            row[o] = b1[o];
            __syncthreads();
            float c = 0.f;
#pragma unroll 8
            for (int h = 0; h < D; h++) c += row[h] * __ldg(W2 + h * D + o);
            d_cvec[o] = c;
        }
    }
    __nv_bfloat16 hi = __float2bfloat16_rn(v);
    d_MThi[o * 512 + r] = hi;
    d_MTlo[o * 512 + r] = __float2bfloat16_rn(v - __bfloat162float(hi));
}

// ---------------- K1: single-pass bucket scatter ----------------
__global__ void k_scatter(const void* ei) {
    int is64 = d_is64;
    int e = blockIdx.x * blockDim.x + threadIdx.x;
    if (e >= N_EDGES) return;
    int dst = load_idx(ei, 1, e, is64);
    int src = load_idx(ei, 0, e, is64);
    int pos = atomicAdd(&d_cur[dst], 1);
    if (pos < BUCKET) {
        d_perm2[(dst << 7) + pos] = make_int2(e, src);
    } else {
        int o = atomicAdd(&d_ovf_cnt, 1);
        if (o < OVF_MAX) d_ovf[o] = make_int3(dst, e, src);
    }
}

// ---------------- K2: atomic-free segment sums (known-good) ----------------
__global__ void k_agg(const float* __restrict__ x, const float* __restrict__ ea) {
    int n = blockIdx.x * 4 + (threadIdx.x >> 5);
    if (n >= NUM_NODES) return;
    int lane = threadIdx.x & 31;
    int deg = d_cur[n];
    if (lane == 0) d_degf[n] = (float)deg;
    int cnt = min(deg, BUCKET);
    const int2* bucket = d_perm2 + ((size_t)n << 7);

    float4 aS = make_float4(0.f, 0.f, 0.f, 0.f);
    float4 aA = make_float4(0.f, 0.f, 0.f, 0.f);

    int j = 0;
    for (; j + 4 <= cnt; j += 4) {
        int2 p0 = __ldg(bucket + j + 0);
        int2 p1 = __ldg(bucket + j + 1);
        int2 p2 = __ldg(bucket + j + 2);
        int2 p3 = __ldg(bucket + j + 3);
        float4 x0 = ldg4(x + (size_t)p0.y * D + lane * 4);
        float4 x1 = ldg4(x + (size_t)p1.y * D + lane * 4);
        float4 x2 = ldg4(x + (size_t)p2.y * D + lane * 4);
        float4 x3 = ldg4(x + (size_t)p3.y * D + lane * 4);
        float4 a0 = ldcs4(ea + (size_t)p0.x * D + lane * 4);
        float4 a1 = ldcs4(ea + (size_t)p1.x * D + lane * 4);
        float4 a2 = ldcs4(ea + (size_t)p2.x * D + lane * 4);
        float4 a3 = ldcs4(ea + (size_t)p3.x * D + lane * 4);
        aS.x += (x0.x + x1.x) + (x2.x + x3.x);
        aS.y += (x0.y + x1.y) + (x2.y + x3.y);
        aS.z += (x0.z + x1.z) + (x2.z + x3.z);
        aS.w += (x0.w + x1.w) + (x2.w + x3.w);
        aA.x += (a0.x + a1.x) + (a2.x + a3.x);
        aA.y += (a0.y + a1.y) + (a2.y + a3.y);
        aA.z += (a0.z + a1.z) + (a2.z + a3.z);
        aA.w += (a0.w + a1.w) + (a2.w + a3.w);
    }
    for (; j < cnt; j++) {
        int2 p = __ldg(bucket + j);
        float4 xv = ldg4(x + (size_t)p.y * D + lane * 4);
        float4 av = ldcs4(ea + (size_t)p.x * D + lane * 4);
        aS.x += xv.x; aS.y += xv.y; aS.z += xv.z; aS.w += xv.w;
        aA.x += av.x; aA.y += av.y; aA.z += av.z; aA.w += av.w;
    }

    if (deg > BUCKET) {
        int cnt_o = d_ovf_cnt;
        if (cnt_o > OVF_MAX) cnt_o = OVF_MAX;
        for (int i = 0; i < cnt_o; i++) {
            int3 v = d_ovf[i];
            if (v.x == n) {
                float4 xv = ldg4(x + (size_t)v.z * D + lane * 4);
                float4 av = ldg4(ea + (size_t)v.y * D + lane * 4);
                aS.x += xv.x; aS.y += xv.y; aS.z += xv.z; aS.w += xv.w;
                aA.x += av.x; aA.y += av.y; aA.z += av.z; aA.w += av.w;
            }
        }
    }

    *(float4*)(d_S + (size_t)n * D + lane * 4) = aS;
    *(float4*)(d_A + (size_t)n * D + lane * 4) = aA;
}

// ---------------- K3: warp-MMA GEMM (mma.sync bf16, 3-term split) ----------------
// Block: 64 nodes x 128 outs, 256 threads (8 warps: 4 m-rows x 2 n-cols).
// Warp tile m16 x n64. K=512 in 8 chunks of 64.
// out = Uhi@Mhi + Uhi@Mlo + Ulo@Mhi  (fp32 accum in registers)
#define AROWB 144                    // 64 bf16 padded to 72 (dodge ldmatrix bank phases)
#define ABUF  (64 * AROWB)           // 9216 B
#define BBUF  (128 * AROWB)          // 18432 B
__global__ void __launch_bounds__(256)
k_gemm_mma(const float* __restrict__ x,
           const float* __restrict__ b2,
           float* __restrict__ out) {
    extern __shared__ __align__(16) char sm[];
    char* Ahi = sm;
    char* Alo = sm + ABUF;
    char* Bhi = sm + 2 * ABUF;
    char* Blo = sm + 2 * ABUF + BBUF;
    uint32_t AhiU = smem_u32(Ahi), AloU = smem_u32(Alo);
    uint32_t BhiU = smem_u32(Bhi), BloU = smem_u32(Blo);

    int t = threadIdx.x;
    int wid = t >> 5, lane = t & 31;
    int wm = wid & 3, wn = wid >> 2;
    int n0 = blockIdx.x * 64;

    // ldmatrix lane address components
    int sub = lane >> 3, lr = lane & 7;
    // A: mat0 rows 0-7, mat1 rows 8-15, mat2 rows 0-7 k+8, mat3 rows 8-15 k+8
    uint32_t a_row = wm * 16 + ((sub & 1) << 3) + lr;
    uint32_t a_col = (uint32_t)((sub >> 1) << 4);
    uint32_t a_off = a_row * AROWB + a_col;
    // B: mat0 rows n..n+7 k, mat1 same rows k+8, mat2 rows n+8..15 k, mat3 k+8
    uint32_t b_row = ((sub >> 1) << 3) + lr;            // + wn*64 + ntp*16 later
    uint32_t b_col = (uint32_t)((sub & 1) << 4);

    float acc[8][4];
#pragma unroll
    for (int i = 0; i < 8; i++)
#pragma unroll
        for (int j = 0; j < 4; j++) acc[i][j] = 0.f;

    for (int c = 0; c < 8; c++) {
        int k0 = c * 64;
        int region = k0 >> 7;
        int kloc = k0 & 127;
        const float* base = (region == 0) ? d_S : (region == 1) ? d_A : x;

        // ---- stage A: 64 rows x 64 k fp32 -> hi/lo bf16 (4 float4 per thread) ----
#pragma unroll
        for (int i = 0; i < 4; i++) {
            int id = t * 4 + i;               // 0..1023
            int row = id >> 4, seg = id & 15; // seg = float4 index within row
            int nn = n0 + row;
            float4 v = make_float4(0.f, 0.f, 0.f, 0.f);
            if (nn < NUM_NODES) {
                v = ldg4(base + (size_t)nn * D + kloc + seg * 4);
                if (region == 3) {
                    float dg = d_degf[nn];
                    v.x *= dg; v.y *= dg; v.z *= dg; v.w *= dg;
                }
            }
            uint2 HI, LO;
            split2(v.x, v.y, HI.x, LO.x);
            split2(v.z, v.w, HI.y, LO.y);
            *(uint2*)(Ahi + row * AROWB + seg * 8) = HI;
            *(uint2*)(Alo + row * AROWB + seg * 8) = LO;
        }
        // ---- stage B: 128 out-rows x 64 k bf16 copies (4 uint4 per thread per buf) ----
#pragma unroll
        for (int i = 0; i < 4; i++) {
            int id = t * 4 + i;               // 0..1023
            int row = id >> 3, q = id & 7;
            *(uint4*)(Bhi + row * AROWB + q * 16) =
                *(const uint4*)(d_MThi + row * 512 + k0 + q * 8);
            *(uint4*)(Blo + row * AROWB + q * 16) =
                *(const uint4*)(d_MTlo + row * 512 + k0 + q * 8);
        }
        __syncthreads();

        // ---- mma: 4 k16-steps ----
#pragma unroll
        for (int s = 0; s < 4; s++) {
            uint32_t ah0, ah1, ah2, ah3, al0, al1, al2, al3;
            ldm_x4(ah0, ah1, ah2, ah3, AhiU + a_off + s * 32);
            ldm_x4(al0, al1, al2, al3, AloU + a_off + s * 32);
#pragma unroll
            for (int ntp = 0; ntp < 4; ntp++) {
                uint32_t boff = (wn * 64 + ntp * 16 + b_row) * AROWB + b_col + s * 32;
                uint32_t bh0, bh1, bh2, bh3, bl0, bl1, bl2, bl3;
                ldm_x4(bh0, bh1, bh2, bh3, BhiU + boff);
                ldm_x4(bl0, bl1, bl2, bl3, BloU + boff);
                mma16816(acc[ntp * 2 + 0], ah0, ah1, ah2, ah3, bh0, bh1);
                mma16816(acc[ntp * 2 + 0], ah0, ah1, ah2, ah3, bl0, bl1);
                mma16816(acc[ntp * 2 + 0], al0, al1, al2, al3, bh0, bh1);
                mma16816(acc[ntp * 2 + 1], ah0, ah1, ah2, ah3, bh2, bh3);
                mma16816(acc[ntp * 2 + 1], ah0, ah1, ah2, ah3, bl2, bl3);
                mma16816(acc[ntp * 2 + 1], al0, al1, al2, al3, bh2, bh3);
            }
        }
        __syncthreads();
    }

    // ---- epilogue: D frag rows = groupID / +8; cols = tig*2, tig*2+1 ----
    int gid = lane >> 2, tig = lane & 3;
    int row0 = n0 + wm * 16 + gid;
    int row1 = row0 + 8;
    float dg0 = (row0 < NUM_NODES) ? d_degf[row0] : 0.f;
    float dg1 = (row1 < NUM_NODES) ? d_degf[row1] : 0.f;
#pragma unroll
    for (int nt = 0; nt < 8; nt++) {
        int col = wn * 64 + nt * 8 + tig * 2;
        float c0 = d_cvec[col], c1 = d_cvec[col + 1];
        float z0 = b2[col], z1 = b2[col + 1];
        if (row0 < NUM_NODES) {
            float2 v = make_float2(acc[nt][0] + dg0 * c0 + z0,
                                   acc[nt][1] + dg0 * c1 + z1);
            *(float2*)(out + (size_t)row0 * D + col) = v;
        }
        if (row1 < NUM_NODES) {
            float2 v = make_float2(acc[nt][2] + dg1 * c0 + z0,
                                   acc[nt][3] + dg1 * c1 + z1);
            *(float2*)(out + (size_t)row1 * D + col) = v;
        }
    }
}

// ---------------- launch ----------------
extern "C" void kernel_launch(void* const* d_in, const int* in_sizes, int n_in,
                              void* d_out, int out_size) {
    const float* x  = (const float*)d_in[0];
    const void*  ei = d_in[1];
    const float* ea = (const float*)d_in[2];
    const float* W1 = (const float*)d_in[3];
    const float* b1 = (const float*)d_in[4];
    const float* W2 = (const float*)d_in[5];
    const float* b2 = (const float*)d_in[6];
    float* out = (float*)d_out;

    const int SMEM = 2 * ABUF + 2 * BBUF;   // 55296 B
    static bool attr_set = false;
    if (!attr_set) {
        cudaFuncSetAttribute(k_gemm_mma, cudaFuncAttributeMaxDynamicSharedMemorySize, SMEM);
        attr_set = true;
    }

    k_setup<<<592, 128>>>(W1, b1, W2, (const int*)ei);
    k_scatter<<<(N_EDGES + 255) / 256, 256>>>(ei);
    k_agg<<<(NUM_NODES + 3) / 4, 128>>>(x, ea);
    k_gemm_mma<<<(NUM_NODES + 63) / 64, 256, SMEM>>>(x, b2, out);
}

// round 11
// speedup vs baseline: 2.1028x; 1.0139x over previous
#include <cuda_runtime.h>
#include <cuda_bf16.h>
#include <cstdint>

#define NUM_NODES 10000
#define N_EDGES   640000
#define D         128
#define BUCKET    128
#define OVF_MAX   4096

// ---------------- device scratch ----------------
__device__ float d_S[NUM_NODES * D];
__device__ float d_A[NUM_NODES * D];
__device__ int   d_cur[NUM_NODES];
__device__ float d_degf[NUM_NODES];
__device__ int2  d_perm2[NUM_NODES * BUCKET];
__device__ int3  d_ovf[OVF_MAX];
__device__ int   d_ovf_cnt;
__device__ __nv_bfloat16 d_MThi[128 * 512];   // fused weights, transposed [out][k], bf16 hi
__device__ __nv_bfloat16 d_MTlo[128 * 512];   // bf16 lo residual
__device__ float d_cvec[D];                   // b1 @ W2a
__device__ int   d_is64;

// ---------------- helpers ----------------
__device__ __forceinline__ int load_idx(const void* ei, int which, int e, int is64) {
    if (is64) {
        const long long* p = (const long long*)ei;
        return (int)__ldg(p + (size_t)which * N_EDGES + e);
    } else {
        const int* p = (const int*)ei;
        return __ldg(p + (size_t)which * N_EDGES + e);
    }
}
__device__ __forceinline__ float4 ldg4(const float* p)  { return __ldg((const float4*)p); }
__device__ __forceinline__ float4 ldcs4(const float* p) { return __ldcs((const float4*)p); }

__device__ __forceinline__ uint32_t smem_u32(const void* p) {
    uint32_t a;
    asm("{ .reg .u64 t; cvta.to.shared.u64 t, %1; cvt.u32.u64 %0, t; }" : "=r"(a) : "l"(p));
    return a;
}

__device__ __forceinline__ void split2(float a, float b, uint32_t& hi, uint32_t& lo) {
    __nv_bfloat162 h = __floats2bfloat162_rn(a, b);
    float2 hf = __bfloat1622float2(h);
    __nv_bfloat162 l = __floats2bfloat162_rn(a - hf.x, b - hf.y);
    hi = *reinterpret_cast<uint32_t*>(&h);
    lo = *reinterpret_cast<uint32_t*>(&l);
}

__device__ __forceinline__ void ldm_x4(uint32_t& r0, uint32_t& r1, uint32_t& r2, uint32_t& r3,
                                       uint32_t addr) {
    asm volatile("ldmatrix.sync.aligned.m8n8.x4.shared.b16 {%0,%1,%2,%3}, [%4];"
                 : "=r"(r0), "=r"(r1), "=r"(r2), "=r"(r3) : "r"(addr));
}
__device__ __forceinline__ void mma16816(float* c,
                                         uint32_t a0, uint32_t a1, uint32_t a2, uint32_t a3,
                                         uint32_t b0, uint32_t b1) {
    asm volatile(
        "mma.sync.aligned.m16n8k16.row.col.f32.bf16.bf16.f32 "
        "{%0,%1,%2,%3}, {%4,%5,%6,%7}, {%8,%9}, {%0,%1,%2,%3};"
        : "+f"(c[0]), "+f"(c[1]), "+f"(c[2]), "+f"(c[3])
        : "r"(a0), "r"(a1), "r"(a2), "r"(a3), "r"(b0), "r"(b1));
}

// ---------------- K0: setup = weight fusion (fp32->bf16 hi/lo, transposed) + probe + zero ----
__global__ void k_setup(const float* __restrict__ W1,
                        const float* __restrict__ b1,
                        const float* __restrict__ W2,
                        const int*   __restrict__ ei_words) {
    int r = blockIdx.x, o = threadIdx.x;   // 128 threads
    if (r >= 512) {
        if (r == 512) {
            int w = ei_words[2 * o + 1];   // high words if int64
            int any = __syncthreads_or(w != 0);
            if (o == 0) { d_is64 = (any == 0) ? 1 : 0; d_ovf_cnt = 0; }
        } else {
            int i = (r - 513) * 128 + o;
            if (i < NUM_NODES) d_cur[i] = 0;
        }
        return;
    }
    __shared__ float row[D];
    float v;
    if (r >= 256 && r < 384) {
        v = W2[(128 + (r - 256)) * D + o];
    } else {
        int w1row = (r < 128) ? r : (r < 256) ? (256 + (r - 128)) : (128 + (r - 384));
        row[o] = W1[w1row * D + o];
        __syncthreads();
        float acc = 0.f;
#pragma unroll 8
        for (int h = 0; h < D; h++) acc += row[h] * __ldg(W2 + h * D + o);
        v = acc;
        if (r == 0) {
            __syncthreads();
            row[o] = b1[o];
            __syncthreads();
            float c = 0.f;
#pragma unroll 8
            for (int h = 0; h < D; h++) c += row[h] * __ldg(W2 + h * D + o);
            d_cvec[o] = c;
        }
    }
    __nv_bfloat16 hi = __float2bfloat16_rn(v);
    d_MThi[o * 512 + r] = hi;
    d_MTlo[o * 512 + r] = __float2bfloat16_rn(v - __bfloat162float(hi));
}

// ---------------- K1: bucket scatter, 4 edges per thread for atomic ILP ----------------
__global__ void k_scatter(const void* ei) {
    int is64 = d_is64;
    int base = blockIdx.x * blockDim.x * 4 + threadIdx.x;
    int dst[4], src[4];
#pragma unroll
    for (int v = 0; v < 4; v++) {
        int e = base + v * 256;
        if (e < N_EDGES) {
            dst[v] = load_idx(ei, 1, e, is64);
            src[v] = load_idx(ei, 0, e, is64);
        } else dst[v] = -1;
    }
#pragma unroll
    for (int v = 0; v < 4; v++) {
        int e = base + v * 256;
        if (dst[v] < 0) continue;
        int pos = atomicAdd(&d_cur[dst[v]], 1);
        if (pos < BUCKET) {
            d_perm2[(dst[v] << 7) + pos] = make_int2(e, src[v]);
        } else {
            int o = atomicAdd(&d_ovf_cnt, 1);
            if (o < OVF_MAX) d_ovf[o] = make_int3(dst[v], e, src[v]);
        }
    }
}

// ---------------- K2: atomic-free segment sums, index-prefetch pipeline ----------------
__global__ void k_agg(const float* __restrict__ x, const float* __restrict__ ea) {
    int n = blockIdx.x * 4 + (threadIdx.x >> 5);
    if (n >= NUM_NODES) return;
    int lane = threadIdx.x & 31;
    int deg = d_cur[n];
    if (lane == 0) d_degf[n] = (float)deg;
    int cnt = min(deg, BUCKET);
    const int2* bucket = d_perm2 + ((size_t)n << 7);

    float4 aS = make_float4(0.f, 0.f, 0.f, 0.f);
    float4 aA = make_float4(0.f, 0.f, 0.f, 0.f);

    int j = 0;
    int2 p0, p1, p2, p3;
    if (j + 4 <= cnt) {
        p0 = __ldg(bucket + 0); p1 = __ldg(bucket + 1);
        p2 = __ldg(bucket + 2); p3 = __ldg(bucket + 3);
    }
    for (; j + 4 <= cnt; j += 4) {
        // data loads for current indices
        float4 x0 = ldg4(x + (size_t)p0.y * D + lane * 4);
        float4 x1 = ldg4(x + (size_t)p1.y * D + lane * 4);
        float4 x2 = ldg4(x + (size_t)p2.y * D + lane * 4);
        float4 x3 = ldg4(x + (size_t)p3.y * D + lane * 4);
        float4 a0 = ldcs4(ea + (size_t)p0.x * D + lane * 4);
        float4 a1 = ldcs4(ea + (size_t)p1.x * D + lane * 4);
        float4 a2 = ldcs4(ea + (size_t)p2.x * D + lane * 4);
        float4 a3 = ldcs4(ea + (size_t)p3.x * D + lane * 4);
        // prefetch next indices (overlaps the data loads above)
        if (j + 8 <= cnt) {
            p0 = __ldg(bucket + j + 4); p1 = __ldg(bucket + j + 5);
            p2 = __ldg(bucket + j + 6); p3 = __ldg(bucket + j + 7);
        }
        aS.x += (x0.x + x1.x) + (x2.x + x3.x);
        aS.y += (x0.y + x1.y) + (x2.y + x3.y);
        aS.z += (x0.z + x1.z) + (x2.z + x3.z);
        aS.w += (x0.w + x1.w) + (x2.w + x3.w);
        aA.x += (a0.x + a1.x) + (a2.x + a3.x);
        aA.y += (a0.y + a1.y) + (a2.y + a3.y);
        aA.z += (a0.z + a1.z) + (a2.z + a3.z);
        aA.w += (a0.w + a1.w) + (a2.w + a3.w);
    }
    for (; j < cnt; j++) {
        int2 p = __ldg(bucket + j);
        float4 xv = ldg4(x + (size_t)p.y * D + lane * 4);
        float4 av = ldcs4(ea + (size_t)p.x * D + lane * 4);
        aS.x += xv.x; aS.y += xv.y; aS.z += xv.z; aS.w += xv.w;
        aA.x += av.x; aA.y += av.y; aA.z += av.z; aA.w += av.w;
    }

    if (deg > BUCKET) {
        int cnt_o = d_ovf_cnt;
        if (cnt_o > OVF_MAX) cnt_o = OVF_MAX;
        for (int i = 0; i < cnt_o; i++) {
            int3 v = d_ovf[i];
            if (v.x == n) {
                float4 xv = ldg4(x + (size_t)v.z * D + lane * 4);
                float4 av = ldg4(ea + (size_t)v.y * D + lane * 4);
                aS.x += xv.x; aS.y += xv.y; aS.z += xv.z; aS.w += xv.w;
                aA.x += av.x; aA.y += av.y; aA.z += av.z; aA.w += av.w;
            }
        }
    }

    *(float4*)(d_S + (size_t)n * D + lane * 4) = aS;
    *(float4*)(d_A + (size_t)n * D + lane * 4) = aA;
}

// ---------------- K3: warp-MMA GEMM, output-split grid ----------------
// Grid (157, 2). Block: 64 nodes x 64 outs, 256 threads (8 warps: 4m x 2n).
// Warp tile m16 x n32. K=512 in 8 chunks of 64.
// out = Uhi@Mhi + Uhi@Mlo + Ulo@Mhi  (fp32 accum in registers)
#define AROWB 144
#define ABUF  (64 * AROWB)           // 9216 B
#define BBUF  (64 * AROWB)           // 9216 B
__global__ void __launch_bounds__(256)
k_gemm_mma(const float* __restrict__ x,
           const float* __restrict__ b2,
           float* __restrict__ out) {
    extern __shared__ __align__(16) char sm[];
    char* Ahi = sm;
    char* Alo = sm + ABUF;
    char* Bhi = sm + 2 * ABUF;
    char* Blo = sm + 2 * ABUF + BBUF;
    uint32_t AhiU = smem_u32(Ahi), AloU = smem_u32(Alo);
    uint32_t BhiU = smem_u32(Bhi), BloU = smem_u32(Blo);

    int t = threadIdx.x;
    int wid = t >> 5, lane = t & 31;
    int wm = wid & 3, wn = wid >> 2;
    int n0 = blockIdx.x * 64;
    int obase = blockIdx.y * 64;

    int sub = lane >> 3, lr = lane & 7;
    uint32_t a_row = wm * 16 + ((sub & 1) << 3) + lr;
    uint32_t a_col = (uint32_t)((sub >> 1) << 4);
    uint32_t a_off = a_row * AROWB + a_col;
    uint32_t b_row = ((sub >> 1) << 3) + lr;
    uint32_t b_col = (uint32_t)((sub & 1) << 4);

    float acc[4][4];
#pragma unroll
    for (int i = 0; i < 4; i++)
#pragma unroll
        for (int j = 0; j < 4; j++) acc[i][j] = 0.f;

    for (int c = 0; c < 8; c++) {
        int k0 = c * 64;
        int region = k0 >> 7;
        int kloc = k0 & 127;
        const float* base = (region == 0) ? d_S : (region == 1) ? d_A : x;

        // stage A: 64 rows x 64 k fp32 -> hi/lo bf16
#pragma unroll
        for (int i = 0; i < 4; i++) {
            int id = t * 4 + i;
            int row = id >> 4, seg = id & 15;
            int nn = n0 + row;
            float4 v = make_float4(0.f, 0.f, 0.f, 0.f);
            if (nn < NUM_NODES) {
                v = ldg4(base + (size_t)nn * D + kloc + seg * 4);
                if (region == 3) {
                    float dg = d_degf[nn];
                    v.x *= dg; v.y *= dg; v.z *= dg; v.w *= dg;
                }
            }
            uint2 HI, LO;
            split2(v.x, v.y, HI.x, LO.x);
            split2(v.z, v.w, HI.y, LO.y);
            *(uint2*)(Ahi + row * AROWB + seg * 8) = HI;
            *(uint2*)(Alo + row * AROWB + seg * 8) = LO;
        }
        // stage B: 64 out-rows (obase..obase+63) x 64 k bf16
#pragma unroll
        for (int i = 0; i < 2; i++) {
            int id = t * 2 + i;               // 0..511
            int row = id >> 3, q = id & 7;
            *(uint4*)(Bhi + row * AROWB + q * 16) =
                *(const uint4*)(d_MThi + (obase + row) * 512 + k0 + q * 8);
            *(uint4*)(Blo + row * AROWB + q * 16) =
                *(const uint4*)(d_MTlo + (obase + row) * 512 + k0 + q * 8);
        }
        __syncthreads();

#pragma unroll
        for (int s = 0; s < 4; s++) {
            uint32_t ah0, ah1, ah2, ah3, al0, al1, al2, al3;
            ldm_x4(ah0, ah1, ah2, ah3, AhiU + a_off + s * 32);
            ldm_x4(al0, al1, al2, al3, AloU + a_off + s * 32);
#pragma unroll
            for (int ntp = 0; ntp < 2; ntp++) {
                uint32_t boff = (wn * 32 + ntp * 16 + b_row) * AROWB + b_col + s * 32;
                uint32_t bh0, bh1, bh2, bh3, bl0, bl1, bl2, bl3;
                ldm_x4(bh0, bh1, bh2, bh3, BhiU + boff);
                ldm_x4(bl0, bl1, bl2, bl3, BloU + boff);
                mma16816(acc[ntp * 2 + 0], ah0, ah1, ah2, ah3, bh0, bh1);
                mma16816(acc[ntp * 2 + 0], ah0, ah1, ah2, ah3, bl0, bl1);
                mma16816(acc[ntp * 2 + 0], al0, al1, al2, al3, bh0, bh1);
                mma16816(acc[ntp * 2 + 1], ah0, ah1, ah2, ah3, bh2, bh3);
                mma16816(acc[ntp * 2 + 1], ah0, ah1, ah2, ah3, bl2, bl3);
                mma16816(acc[ntp * 2 + 1], al0, al1, al2, al3, bh2, bh3);
            }
        }
        __syncthreads();
    }

    // epilogue
    int gid = lane >> 2, tig = lane & 3;
    int row0 = n0 + wm * 16 + gid;
    int row1 = row0 + 8;
    float dg0 = (row0 < NUM_NODES) ? d_degf[row0] : 0.f;
    float dg1 = (row1 < NUM_NODES) ? d_degf[row1] : 0.f;
#pragma unroll
    for (int nt = 0; nt < 4; nt++) {
        int col = obase + wn * 32 + nt * 8 + tig * 2;
        float c0 = d_cvec[col], c1 = d_cvec[col + 1];
        float z0 = b2[col], z1 = b2[col + 1];
        if (row0 < NUM_NODES) {
            float2 v = make_float2(acc[nt][0] + dg0 * c0 + z0,
                                   acc[nt][1] + dg0 * c1 + z1);
            *(float2*)(out + (size_t)row0 * D + col) = v;
        }
        if (row1 < NUM_NODES) {
            float2 v = make_float2(acc[nt][2] + dg1 * c0 + z0,
                                   acc[nt][3] + dg1 * c1 + z1);
            *(float2*)(out + (size_t)row1 * D + col) = v;
        }
    }
}

// ---------------- launch ----------------
extern "C" void kernel_launch(void* const* d_in, const int* in_sizes, int n_in,
                              void* d_out, int out_size) {
    const float* x  = (const float*)d_in[0];
    const void*  ei = d_in[1];
    const float* ea = (const float*)d_in[2];
    const float* W1 = (const float*)d_in[3];
    const float* b1 = (const float*)d_in[4];
    const float* W2 = (const float*)d_in[5];
    const float* b2 = (const float*)d_in[6];
    float* out = (float*)d_out;

    const int SMEM = 2 * ABUF + 2 * BBUF;   // 36864 B
    static bool attr_set = false;
    if (!attr_set) {
        cudaFuncSetAttribute(k_gemm_mma, cudaFuncAttributeMaxDynamicSharedMemorySize, SMEM);
        attr_set = true;
    }

    k_setup<<<592, 128>>>(W1, b1, W2, (const int*)ei);
    k_scatter<<<(N_EDGES + 1023) / 1024, 256>>>(ei);
    k_agg<<<(NUM_NODES + 3) / 4, 128>>>(x, ea);
    dim3 gg((NUM_NODES + 63) / 64, 2);
    k_gemm_mma<<<gg, 256, SMEM>>>(x, b2, out);
}